// round 16
// baseline (speedup 1.0000x reference)
#include <cuda_runtime.h>
#include <cuda_fp16.h>
#include <math.h>
#include <stdint.h>

// Problem constants
#define BB 4
#define TT 2048
#define CC 1024
#define HH 16
#define DD 64
#define MTOK (BB * TT)          // 8192 tokens
#define N_QKV (3 * CC)          // 3072
#define NKC 16                  // 64-wide K blocks per 1024

#define LOG2E 1.4426950408889634f
#define NWORK 152               // persistent workers (GB300: 152 SMs)

// ---------------------------------------------------------------------------
// Scratch (allocation-free rule: __device__ globals) — fp16 single precision
// ---------------------------------------------------------------------------
__device__ __half g_x16[(size_t)MTOK * CC];
__device__ __half g_y16[(size_t)MTOK * CC];
__device__ __half g_wqkv16[(size_t)N_QKV * CC];
__device__ __half g_wproj16[(size_t)CC * CC];
// attention operand tiles (per (b,h), SW128 swizzled fp16)
__device__ __half g_q16[(size_t)BB * HH * 16 * 8192];
__device__ __half g_k16[(size_t)BB * HH * 16 * 8192];
__device__ __half g_v16[(size_t)BB * HH * 32 * 4096];

// ---------------------------------------------------------------------------
// PTX helpers (base sm_103 target — NO tcgen05)
// ---------------------------------------------------------------------------
__device__ __forceinline__ uint32_t smem_u32(const void* p) {
    uint32_t a;
    asm("{ .reg .u64 t; cvta.to.shared.u64 t, %1; cvt.u32.u64 %0, t; }" : "=r"(a) : "l"(p));
    return a;
}

#define SWZ128(off) ((off) ^ (((off) >> 3) & 0x70))

#define MBAR_INIT(addr, cnt) \
    asm volatile("mbarrier.init.shared.b64 [%0], %1;" :: "r"(addr), "r"(cnt) : "memory")

#define MBAR_EXPECT_TX(addr, bytes) \
    asm volatile("mbarrier.arrive.expect_tx.shared.b64 _, [%0], %1;" :: "r"(addr), "r"(bytes) : "memory")

#define MBAR_ARRIVE(addr) \
    asm volatile("mbarrier.arrive.shared.b64 _, [%0];" :: "r"(addr) : "memory")

__device__ __forceinline__ void mbar_wait(uint32_t mbar, uint32_t parity) {
    uint32_t done;
    asm volatile(
        "{\n\t.reg .pred p;\n\t"
        "mbarrier.try_wait.parity.acquire.cta.shared::cta.b64 p, [%1], %2;\n\t"
        "selp.b32 %0, 1, 0, p;\n\t}"
        : "=r"(done) : "r"(mbar), "r"(parity) : "memory");
    if (!done) {
        asm volatile(
            "{\n\t.reg .pred P1;\n\t"
            "WL_%=:\n\t"
            "mbarrier.try_wait.parity.acquire.cta.shared::cta.b64 P1, [%0], %1, 0x989680;\n\t"
            "@P1 bra.uni WD_%=;\n\t"
            "bra.uni WL_%=;\n\t"
            "WD_%=:\n\t}"
            :: "r"(mbar), "r"(parity) : "memory");
    }
}

__device__ __forceinline__ void bulk_g2s(uint32_t dst, const void* src, uint32_t bytes, uint32_t mbar) {
    asm volatile(
        "cp.async.bulk.shared::cluster.global.mbarrier::complete_tx::bytes [%0], [%1], %2, [%3];"
        :: "r"(dst), "l"(src), "r"(bytes), "r"(mbar) : "memory");
}

#define FENCE_ASYNC() asm volatile("fence.proxy.async.shared::cta;" ::: "memory")

__device__ __forceinline__ void ldsm_x4(uint32_t& r0, uint32_t& r1, uint32_t& r2, uint32_t& r3,
                                        uint32_t addr) {
    asm volatile("ldmatrix.sync.aligned.m8n8.x4.shared.b16 {%0,%1,%2,%3}, [%4];"
                 : "=r"(r0), "=r"(r1), "=r"(r2), "=r"(r3) : "r"(addr));
}

__device__ __forceinline__ void mma_f16(float* d, const uint32_t* a, const uint32_t* b) {
    asm volatile(
        "mma.sync.aligned.m16n8k16.row.col.f32.f16.f16.f32 "
        "{%0,%1,%2,%3}, {%4,%5,%6,%7}, {%8,%9}, {%0,%1,%2,%3};"
        : "+f"(d[0]), "+f"(d[1]), "+f"(d[2]), "+f"(d[3])
        : "r"(a[0]), "r"(a[1]), "r"(a[2]), "r"(a[3]), "r"(b[0]), "r"(b[1]));
}

__device__ __forceinline__ float ex2(float x) {
    float r;
    asm("ex2.approx.f32 %0, %1;" : "=f"(r) : "f"(x));
    return r;
}
__device__ __forceinline__ uint32_t ex2h2(uint32_t x) {
    uint32_t r;
    asm("ex2.approx.f16x2 %0, %1;" : "=r"(r) : "r"(x));
    return r;
}

__device__ __forceinline__ uint32_t packh2(float a, float b) {
    __half2 h = __floats2half2_rn(a, b);
    return *(uint32_t*)&h;
}

// ---------------------------------------------------------------------------
// Combined prep kernel (identical to R14)
// ---------------------------------------------------------------------------
__global__ __launch_bounds__(256) void prep_all_kernel(
    const float* __restrict__ x, __half* __restrict__ x16,
    const float* __restrict__ Wq, __half* __restrict__ wq16,
    const float* __restrict__ Wp, __half* __restrict__ wp16)
{
    __shared__ float s[64][128];
    const int id = blockIdx.x;
    const int t = threadIdx.x;

    if (id < 1024) {
        const int kc = id & 15;
        const int mt = id >> 4;
        const int r0 = t >> 3;
        const int c8 = t & 7;
        char* bh = (char*)(x16 + ((size_t)mt * NKC + kc) * 8192);
#pragma unroll
        for (int j = 0; j < 4; j++) {
            const int r = r0 + j * 32;
            const float* src = x + (size_t)(mt * 128 + r) * CC + kc * 64 + c8 * 8;
            float4 v0 = ((const float4*)src)[0];
            float4 v1 = ((const float4*)src)[1];
            __align__(16) __half h8[8];
            h8[0] = __float2half_rn(v0.x); h8[1] = __float2half_rn(v0.y);
            h8[2] = __float2half_rn(v0.z); h8[3] = __float2half_rn(v0.w);
            h8[4] = __float2half_rn(v1.x); h8[5] = __float2half_rn(v1.y);
            h8[6] = __float2half_rn(v1.z); h8[7] = __float2half_rn(v1.w);
            uint32_t off = SWZ128((uint32_t)(r * 128 + c8 * 16));
            *(uint4*)(bh + off) = *(const uint4*)h8;
        }
        return;
    }

    const bool isQ = (id < 1408);
    const int v = isQ ? (id - 1024) : (id - 1408);
    const int kc = v & 15;
    const int nt = v >> 4;
    const float* W = isQ ? Wq : Wp;
    __half* oh = isQ ? wq16 : wp16;
    const int N = isQ ? N_QKV : CC;

    for (int idx = t; idx < 64 * 128; idx += 256) {
        int r = idx >> 7, n = idx & 127;
        s[r][n] = W[(size_t)(kc * 64 + r) * N + nt * 128 + n];
    }
    __syncthreads();

    const int np = t & 127;
    const int c0 = (t >> 7) * 4;
    char* bh = (char*)(oh + ((size_t)nt * NKC + kc) * 8192);

#pragma unroll
    for (int c = c0; c < c0 + 4; c++) {
        __align__(16) __half h8[8];
#pragma unroll
        for (int j = 0; j < 8; j++) h8[j] = __float2half_rn(s[c * 8 + j][np]);
        uint32_t off = SWZ128((uint32_t)(np * 128 + c * 16));
        *(uint4*)(bh + off) = *(const uint4*)h8;
    }
}

// ---------------------------------------------------------------------------
// PERSISTENT phase-continuous mma.sync fp16 GEMM: 152 CTAs, each strides over
// tiles (t = worker + i*NWORK). Barriers init once; global chunk counters;
// inline tid-0 producer flows across tile boundaries (epilogue overlaps next
// tile's loads). BK=64 inner loop identical to R14. 4 stages + dedicated
// 66KB V-transpose scratch. MODE 0: fp32+bias. MODE 1: QKV fused epilogue.
// ---------------------------------------------------------------------------
#define G_STAGE  32768u      // A 16K | B 16K
#define G_NSTAGE 4
#define G_SCRATCH 66048u     // 128*129*4 fp32 V-transpose scratch
#define GEMM_SMEM (1024u + G_NSTAGE * G_STAGE + G_SCRATCH)   // 198144 B

template <int MODE>
__global__ __launch_bounds__(256, 1) void gemm_mma_kernel(
    const __half* __restrict__ A_, const __half* __restrict__ B_,
    const float* __restrict__ bias, float* __restrict__ C, int NX, int NTILES,
    __half* __restrict__ oQ, __half* __restrict__ oK, __half* __restrict__ oV)
{
    extern __shared__ __align__(1024) char smem[];
    const uint32_t sbase = smem_u32(smem);
    const int tid = threadIdx.x;
    const int worker = (int)blockIdx.x;
    const int N = NX * 128;

    const uint32_t stage0 = sbase + 1024;
    float* sf = (float*)(smem + 1024 + G_NSTAGE * G_STAGE);   // V scratch

    if (tid == 0) {
#pragma unroll
        for (int s = 0; s < G_NSTAGE; s++) {
            MBAR_INIT(sbase + 8 + 8 * s, 1);
            MBAR_INIT(sbase + 48 + 8 * s, 8);
        }
    }
    __syncthreads();

    const int w = tid >> 5, l = tid & 31;
    const int mrow = (w >> 2) * 64;
    const int ncol = (w & 3) * 32;
    const int mat = l >> 3;
    const int rin = l & 7;
    const int a_row_off = rin + ((mat & 1) << 3);
    const int a_kb_off  = (mat >> 1) << 4;
    const int b_row_off = rin + ((mat >> 1) << 3);
    const int b_kb_off  = (mat & 1) << 4;
    const int lr = l >> 2;
    const int lc = (l & 3) * 2;

    // ---- producer cursor (tid 0 only) ----
    int tp = worker;
    int kt_p = 0;
    int gp = 0;
    const char* pA_p = (const char*)(A_ + (size_t)(tp < NTILES ? tp / NX : 0) * NKC * 8192);
    const char* pB_p = (const char*)(B_ + (size_t)(tp < NTILES ? tp % NX : 0) * NKC * 8192);

    if (tid == 0 && tp < NTILES) {
#pragma unroll
        for (int i = 0; i < G_NSTAGE; i++) {   // first tile has 16 >= 4 chunks
            const int s = gp % G_NSTAGE;
            mbar_wait(sbase + 48 + 8 * s, 1);  // fresh: immediate
            FENCE_ASYNC();
            const uint32_t mb = sbase + 8 + 8 * s;
            const uint32_t st = stage0 + s * G_STAGE;
            MBAR_EXPECT_TX(mb, G_STAGE);
            bulk_g2s(st + 0,     pA_p + (size_t)kt_p * 16384, 16384, mb);
            bulk_g2s(st + 16384, pB_p + (size_t)kt_p * 16384, 16384, mb);
            kt_p++; gp++;
        }
    }

    int gc = 0;
    for (int t = worker; t < NTILES; t += NWORK) {
        const int nt = t % NX;
        const int mt = t / NX;

        float acc[4][4][4];
#pragma unroll
        for (int i = 0; i < 4; i++)
#pragma unroll
            for (int j = 0; j < 4; j++)
#pragma unroll
                for (int k = 0; k < 4; k++) acc[i][j][k] = 0.f;

        for (int c = 0; c < NKC; c++) {
            const int s = gc % G_NSTAGE;
            const uint32_t ph = (uint32_t)((gc / G_NSTAGE) & 1);
            mbar_wait(sbase + 8 + 8 * s, ph);

            const uint32_t stA = stage0 + s * G_STAGE;
            const uint32_t stB = stA + 16384;

#pragma unroll
            for (int ks = 0; ks < 4; ks++) {
                const int kb = ks * 32;
                uint32_t bf[4][2];
#pragma unroll
                for (int n16 = 0; n16 < 2; n16++) {
                    int row = ncol + n16 * 16 + b_row_off;
                    uint32_t off = (uint32_t)(row * 128) +
                                   (uint32_t)((kb + b_kb_off) ^ ((row & 7) << 4));
                    ldsm_x4(bf[n16 * 2][0], bf[n16 * 2][1],
                            bf[n16 * 2 + 1][0], bf[n16 * 2 + 1][1], stB + off);
                }
#pragma unroll
                for (int m16 = 0; m16 < 4; m16++) {
                    int row = mrow + m16 * 16 + a_row_off;
                    uint32_t off = (uint32_t)(row * 128) +
                                   (uint32_t)((kb + a_kb_off) ^ ((row & 7) << 4));
                    uint32_t a[4];
                    ldsm_x4(a[0], a[1], a[2], a[3], stA + off);
#pragma unroll
                    for (int n8 = 0; n8 < 4; n8++) mma_f16(acc[m16][n8], a, bf[n8]);
                }
            }

            if (l == 0) MBAR_ARRIVE(sbase + 48 + 8 * s);

            // producer pump: one chunk, flows across tile boundaries
            if (tid == 0 && tp < NTILES) {
                if (kt_p == NKC) {
                    kt_p = 0;
                    tp += NWORK;
                    if (tp < NTILES) {
                        pA_p = (const char*)(A_ + (size_t)(tp / NX) * NKC * 8192);
                        pB_p = (const char*)(B_ + (size_t)(tp % NX) * NKC * 8192);
                    }
                }
                if (tp < NTILES) {
                    const int sp = gp % G_NSTAGE;
                    mbar_wait(sbase + 48 + 8 * sp, (uint32_t)(((gp / G_NSTAGE) & 1) ^ 1));
                    FENCE_ASYNC();
                    const uint32_t mb = sbase + 8 + 8 * sp;
                    const uint32_t st = stage0 + sp * G_STAGE;
                    MBAR_EXPECT_TX(mb, G_STAGE);
                    bulk_g2s(st + 0,     pA_p + (size_t)kt_p * 16384, 16384, mb);
                    bulk_g2s(st + 16384, pB_p + (size_t)kt_p * 16384, 16384, mb);
                    kt_p++; gp++;
                }
            }
            gc++;
        }

        // ---- epilogue for tile t (overlaps producer's next-tile loads) ----
        if constexpr (MODE == 0) {
#pragma unroll
            for (int m16 = 0; m16 < 4; m16++) {
                const size_t r0 = (size_t)(mt * 128 + mrow + m16 * 16 + lr);
                float* c0p = C + r0 * N;
                float* c1p = c0p + (size_t)8 * N;
#pragma unroll
                for (int n8 = 0; n8 < 4; n8++) {
                    const int col = nt * 128 + ncol + n8 * 8 + lc;
                    const float bx = bias[col], by = bias[col + 1];
                    float2 v0 = make_float2(acc[m16][n8][0] + bx, acc[m16][n8][1] + by);
                    float2 v1 = make_float2(acc[m16][n8][2] + bx, acc[m16][n8][3] + by);
                    *(float2*)(c0p + col) = v0;
                    *(float2*)(c1p + col) = v1;
                }
            }
        } else {
            const int b_ = mt >> 4;
            const int qt_ = mt & 15;
            if (nt < 16) {
                const bool isQ = (nt < 8);
                __half* oh = isQ ? oQ : oK;
                const float scale = isQ ? (0.125f * LOG2E) : 1.0f;
                const int nth = isQ ? nt : nt - 8;
#pragma unroll
                for (int m16 = 0; m16 < 4; m16++) {
                    const int rl0 = mrow + m16 * 16 + lr;
#pragma unroll
                    for (int n8 = 0; n8 < 4; n8++) {
                        const int cl = ncol + n8 * 8 + lc;
                        const int hh2 = cl >> 6;
                        const int d = cl & 63;
                        const float bx = bias[nt * 128 + cl];
                        const float by = bias[nt * 128 + cl + 1];
                        const size_t tb =
                            ((size_t)(b_ * HH + 2 * nth + hh2) * 16 + qt_) * 8192;
                        char* th = (char*)(oh + tb);
                        const uint32_t h0 = packh2((acc[m16][n8][0] + bx) * scale,
                                                   (acc[m16][n8][1] + by) * scale);
                        const uint32_t off0 = SWZ128((uint32_t)(rl0 * 128 + d * 2));
                        *(uint32_t*)(th + off0) = h0;
                        const uint32_t h1 = packh2((acc[m16][n8][2] + bx) * scale,
                                                   (acc[m16][n8][3] + by) * scale);
                        const uint32_t off1 = SWZ128((uint32_t)((rl0 + 8) * 128 + d * 2));
                        *(uint32_t*)(th + off1) = h1;
                    }
                }
            } else {
                // V transpose via dedicated scratch (no stage alias)
#pragma unroll
                for (int m16 = 0; m16 < 4; m16++) {
                    const int rl0 = mrow + m16 * 16 + lr;
#pragma unroll
                    for (int n8 = 0; n8 < 4; n8++) {
                        const int cl = ncol + n8 * 8 + lc;
                        const float bx = bias[nt * 128 + cl];
                        const float by = bias[nt * 128 + cl + 1];
                        sf[rl0 * 129 + cl]           = acc[m16][n8][0] + bx;
                        sf[rl0 * 129 + cl + 1]       = acc[m16][n8][1] + by;
                        sf[(rl0 + 8) * 129 + cl]     = acc[m16][n8][2] + bx;
                        sf[(rl0 + 8) * 129 + cl + 1] = acc[m16][n8][3] + by;
                    }
                }
                __syncthreads();
                const int ntv = nt - 16;
                for (int it = tid; it < 2048; it += 256) {
                    const int hh2 = it >> 10;
                    const int rem = it & 1023;
                    const int kt2loc = rem >> 9;
                    const int d = (rem >> 3) & 63;
                    const int oct = rem & 7;
                    __align__(16) __half h8[8];
#pragma unroll
                    for (int e = 0; e < 8; e++) {
                        const int key = kt2loc * 64 + oct * 8 + e;
                        h8[e] = __float2half_rn(sf[key * 129 + hh2 * 64 + d]);
                    }
                    const size_t tb =
                        ((size_t)(b_ * HH + 2 * ntv + hh2) * 32 + qt_ * 2 + kt2loc) * 4096;
                    const uint32_t off = SWZ128((uint32_t)(d * 128 + oct * 16));
                    *(uint4*)((char*)(oV + tb) + off) = *(const uint4*)h8;
                }
                __syncthreads();   // no warp starts next V tile's sf writes early
            }
        }
    }
}

// ---------------------------------------------------------------------------
// PERSISTENT flash attention, PHASE-CONTINUOUS across jobs (identical to R14)
// ---------------------------------------------------------------------------
#define ATT_STAGE 32768u        // K 16K | V 16K
#define A_NSTAGE 5
#define ATT_SMEM  (1024u + 2u * 16384u + A_NSTAGE * ATT_STAGE)   // 197632 B
#define NJOBS 1024
#define ONESH2 0x3C003C00u      // half2(1.0, 1.0)

__global__ __launch_bounds__(256) void flash_mma_kernel(
    const __half* __restrict__ Q_, const __half* __restrict__ K_,
    const __half* __restrict__ V_, __half* __restrict__ oY)
{
    extern __shared__ __align__(1024) char smem[];
    const uint32_t sbase = smem_u32(smem);
    const int tid = threadIdx.x;
    const int worker = (int)blockIdx.x;

    const uint32_t mb_qf = sbase + 8;
    const uint32_t mb_qe = sbase + 24;
    const uint32_t mb_f  = sbase + 40;
    const uint32_t mb_e  = sbase + 88;
    const uint32_t sQ0 = sbase + 1024;
    const uint32_t stage0 = sbase + 1024 + 32768;

    if (tid == 0) {
        MBAR_INIT(mb_qf + 0, 1); MBAR_INIT(mb_qf + 8, 1);
        MBAR_INIT(mb_qe + 0, 8); MBAR_INIT(mb_qe + 8, 8);
#pragma unroll
        for (int s = 0; s < A_NSTAGE; s++) {
            MBAR_INIT(mb_f + 8 * s, 1);
            MBAR_INIT(mb_e + 8 * s, 8);
        }
    }
    __syncthreads();

    const int w = tid >> 5, l = tid & 31;
    const int mat = l >> 3, rin = l & 7;
    const int a_row_off = rin + ((mat & 1) << 3);
    const int a_kb_off  = (mat >> 1) << 4;
    const int b_row_off = rin + ((mat >> 1) << 3);
    const int b_kb_off  = (mat & 1) << 4;
    const int lr = l >> 2, qp = l & 3;

    const uint32_t ones[2] = {ONESH2, ONESH2};

    int pp = 0;
    int rank_p = worker;
    int kt_p = 0;
    int ntp = 16 - (rank_p >> 6);
    int jq = 0;
    int gp = 0;

    if (tid == 0) {
        mbar_wait(mb_qe + 0, 1);
        MBAR_EXPECT_TX(mb_qf + 0, 16384);
        {
            const int bhp = rank_p & 63;
            const int qtp = 15 - (rank_p >> 6);
            bulk_g2s(sQ0, (const char*)(Q_ + ((size_t)bhp * 16 + qtp) * 8192),
                     16384, mb_qf + 0);
        }
        jq = 1;
#pragma unroll
        for (int i = 0; i < A_NSTAGE; i++) {
            const int s = gp % A_NSTAGE;
            mbar_wait(mb_e + 8 * s, 1);
            FENCE_ASYNC();
            const uint32_t mb = mb_f + 8 * s;
            const uint32_t st = stage0 + s * ATT_STAGE;
            MBAR_EXPECT_TX(mb, ATT_STAGE);
            const int bhp = rank_p & 63;
            bulk_g2s(st + 0,
                     (const char*)(K_ + (size_t)bhp * 16 * 8192) + (size_t)kt_p * 16384,
                     16384, mb);
            bulk_g2s(st + 16384,
                     (const char*)(V_ + (size_t)bhp * 32 * 4096) + (size_t)kt_p * 16384,
                     16384, mb);
            kt_p++; gp++;
        }
    }

    int gc = 0;
    for (int p = 0;; p++) {
        const int rank = p * NWORK + ((p & 1) ? (NWORK - 1 - worker) : worker);
        if (rank >= NJOBS) break;
        const int qt = 15 - (rank >> 6);
        const int bh_idx = rank & 63;
        const int b = bh_idx >> 4;
        const int h = bh_idx & 15;
        const int ntiles = qt + 1;
        const int slot = p & 1;

        mbar_wait(mb_qf + 8 * slot, (uint32_t)((p >> 1) & 1));
        uint32_t qf[4][4];
#pragma unroll
        for (int ks = 0; ks < 4; ks++) {
            int row = w * 16 + a_row_off;
            uint32_t off = (uint32_t)(row * 128) +
                           (uint32_t)((ks * 32 + a_kb_off) ^ ((row & 7) << 4));
            ldsm_x4(qf[ks][0], qf[ks][1], qf[ks][2], qf[ks][3],
                    sQ0 + 16384u * slot + off);
        }
        if (l == 0) MBAR_ARRIVE(mb_qe + 8 * slot);

        float acc_o[8][4];
#pragma unroll
        for (int j = 0; j < 8; j++)
#pragma unroll
            for (int e = 0; e < 4; e++) acc_o[j][e] = 0.f;
        float acc_l[4] = {0.f, 0.f, 0.f, 0.f};
        float m0 = -1e30f, m1 = -1e30f;

        for (int kt = 0; kt < ntiles; kt++) {
            const int s = gc % A_NSTAGE;
            const uint32_t phs = (uint32_t)((gc / A_NSTAGE) & 1);
            mbar_wait(mb_f + 8 * s, phs);
            const uint32_t stK = stage0 + s * ATT_STAGE;
            const uint32_t stV = stK + 16384;

            float acc_s[16][4];
#pragma unroll
            for (int j = 0; j < 16; j++)
#pragma unroll
                for (int e = 0; e < 4; e++) acc_s[j][e] = 0.f;

#pragma unroll
            for (int ks = 0; ks < 4; ks++) {
                const uint32_t kb = (uint32_t)(ks * 32 + b_kb_off);
#pragma unroll
                for (int g = 0; g < 8; g++) {
                    int row = g * 16 + b_row_off;
                    uint32_t off = (uint32_t)(row * 128) + (kb ^ (uint32_t)((row & 7) << 4));
                    uint32_t kf[4];
                    ldsm_x4(kf[0], kf[1], kf[2], kf[3], stK + off);
                    mma_f16(acc_s[2 * g],     qf[ks], kf);
                    mma_f16(acc_s[2 * g + 1], qf[ks], kf + 2);
                }
            }

            if (kt == qt) {
                const int rr0 = w * 16 + lr, rr1 = rr0 + 8;
#pragma unroll
                for (int j = 0; j < 16; j++) {
                    const int c0 = j * 8 + qp * 2;
                    if (c0     > rr0) acc_s[j][0] = -1e30f;
                    if (c0 + 1 > rr0) acc_s[j][1] = -1e30f;
                    if (c0     > rr1) acc_s[j][2] = -1e30f;
                    if (c0 + 1 > rr1) acc_s[j][3] = -1e30f;
                }
            }

            float t0 = -1e30f, t1 = -1e30f;
#pragma unroll
            for (int j = 0; j < 16; j++) {
                t0 = fmaxf(t0, fmaxf(acc_s[j][0], acc_s[j][1]));
                t1 = fmaxf(t1, fmaxf(acc_s[j][2], acc_s[j][3]));
            }
            t0 = fmaxf(t0, __shfl_xor_sync(0xffffffffu, t0, 1));
            t0 = fmaxf(t0, __shfl_xor_sync(0xffffffffu, t0, 2));
            t1 = fmaxf(t1, __shfl_xor_sync(0xffffffffu, t1, 1));
            t1 = fmaxf(t1, __shfl_xor_sync(0xffffffffu, t1, 2));

            const float mn0 = fmaxf(m0, t0);
            const float mn1 = fmaxf(m1, t1);
            const float cr0 = ex2(m0 - mn0);
            const float cr1 = ex2(m1 - mn1);
            m0 = mn0; m1 = mn1;
            acc_l[0] *= cr0; acc_l[1] *= cr0;
            acc_l[2] *= cr1; acc_l[3] *= cr1;
#pragma unroll
            for (int j = 0; j < 8; j++) {
                acc_o[j][0] *= cr0; acc_o[j][1] *= cr0;
                acc_o[j][2] *= cr1; acc_o[j][3] *= cr1;
            }

#pragma unroll
            for (int kc = 0; kc < 8; kc++) {
                uint32_t pf[4];
#pragma unroll
                for (int jj = 0; jj < 2; jj++) {
                    const int j = 2 * kc + jj;
                    pf[jj * 2 + 0] = ex2h2(packh2(acc_s[j][0] - mn0, acc_s[j][1] - mn0));
                    pf[jj * 2 + 1] = ex2h2(packh2(acc_s[j][2] - mn1, acc_s[j][3] - mn1));
                }
                mma_f16(acc_l, pf, ones);

                const uint32_t vb = stV + ((kc < 4) ? 0u : 8192u);
                const uint32_t kb = (uint32_t)((kc & 3) * 32 + b_kb_off);
#pragma unroll
                for (int g = 0; g < 4; g++) {
                    int row = g * 16 + b_row_off;
                    uint32_t off = (uint32_t)(row * 128) + (kb ^ (uint32_t)((row & 7) << 4));
                    uint32_t vf[4];
                    ldsm_x4(vf[0], vf[1], vf[2], vf[3], vb + off);
                    mma_f16(acc_o[2 * g],     pf, vf);
                    mma_f16(acc_o[2 * g + 1], pf, vf + 2);
                }
            }

            if (l == 0) MBAR_ARRIVE(mb_e + 8 * s);

            if (tid == 0 && rank_p < NJOBS) {
                if (kt_p == ntp) {
                    pp++;
                    rank_p = pp * NWORK + ((pp & 1) ? (NWORK - 1 - worker) : worker);
                    if (rank_p < NJOBS) {
                        ntp = 16 - (rank_p >> 6);
                        kt_p = 0;
                        const int qslot = jq & 1;
                        mbar_wait(mb_qe + 8 * qslot, (uint32_t)(((jq >> 1) & 1) ^ 1));
                        FENCE_ASYNC();
                        MBAR_EXPECT_TX(mb_qf + 8 * qslot, 16384);
                        const int bhp = rank_p & 63;
                        const int qtp = 15 - (rank_p >> 6);
                        bulk_g2s(sQ0 + 16384u * qslot,
                                 (const char*)(Q_ + ((size_t)bhp * 16 + qtp) * 8192),
                                 16384, mb_qf + 8 * qslot);
                        jq++;
                    }
                }
                if (rank_p < NJOBS) {
                    const int sp = gp % A_NSTAGE;
                    mbar_wait(mb_e + 8 * sp, (uint32_t)(((gp / A_NSTAGE) & 1) ^ 1));
                    FENCE_ASYNC();
                    const uint32_t mb = mb_f + 8 * sp;
                    const uint32_t st = stage0 + sp * ATT_STAGE;
                    MBAR_EXPECT_TX(mb, ATT_STAGE);
                    const int bhp = rank_p & 63;
                    bulk_g2s(st + 0,
                             (const char*)(K_ + (size_t)bhp * 16 * 8192) +
                                 (size_t)kt_p * 16384, 16384, mb);
                    bulk_g2s(st + 16384,
                             (const char*)(V_ + (size_t)bhp * 32 * 4096) +
                                 (size_t)kt_p * 16384, 16384, mb);
                    kt_p++; gp++;
                }
            }
            gc++;
        }

        const float inv0 = 1.f / acc_l[0];
        const float inv1 = 1.f / acc_l[2];

        const size_t tb = ((size_t)(b * 16 + qt) * NKC + h) * 8192;
        char* th = (char*)(oY + tb);
        const int rl0 = w * 16 + lr;
#pragma unroll
        for (int j = 0; j < 8; j++) {
            const int dc = j * 8 + qp * 2;
            const uint32_t h0 = packh2(acc_o[j][0] * inv0, acc_o[j][1] * inv0);
            const uint32_t off0 = SWZ128((uint32_t)(rl0 * 128 + dc * 2));
            *(uint32_t*)(th + off0) = h0;
            const uint32_t h1 = packh2(acc_o[j][2] * inv1, acc_o[j][3] * inv1);
            const uint32_t off1 = SWZ128((uint32_t)((rl0 + 8) * 128 + dc * 2));
            *(uint32_t*)(th + off1) = h1;
        }
    }
}

// ---------------------------------------------------------------------------
// Launch
// ---------------------------------------------------------------------------
extern "C" void kernel_launch(void* const* d_in, const int* in_sizes, int n_in,
                              void* d_out, int out_size)
{
    const float* x     = (const float*)d_in[0];
    const float* Wqkv  = (const float*)d_in[1];
    const float* bqkv  = (const float*)d_in[2];
    const float* Wproj = (const float*)d_in[3];
    const float* bproj = (const float*)d_in[4];
    float* out = (float*)d_out;

    __half *x16, *y16, *wq16, *wp16, *q16, *k16, *v16;
    cudaGetSymbolAddress((void**)&x16, g_x16);
    cudaGetSymbolAddress((void**)&y16, g_y16);
    cudaGetSymbolAddress((void**)&wq16, g_wqkv16);
    cudaGetSymbolAddress((void**)&wp16, g_wproj16);
    cudaGetSymbolAddress((void**)&q16, g_q16);
    cudaGetSymbolAddress((void**)&k16, g_k16);
    cudaGetSymbolAddress((void**)&v16, g_v16);

    cudaFuncSetAttribute(gemm_mma_kernel<0>,
                         cudaFuncAttributeMaxDynamicSharedMemorySize, GEMM_SMEM);
    cudaFuncSetAttribute(gemm_mma_kernel<1>,
                         cudaFuncAttributeMaxDynamicSharedMemorySize, GEMM_SMEM);
    cudaFuncSetAttribute(flash_mma_kernel,
                         cudaFuncAttributeMaxDynamicSharedMemorySize, ATT_SMEM);

    // Combined prep (x + both weight transposes, fp16)
    prep_all_kernel<<<1536, 256>>>(x, x16, Wqkv, wq16, Wproj, wp16);

    // Persistent QKV GEMM with fused Q/K/V-tile epilogue (NX=24, 1536 tiles)
    gemm_mma_kernel<1><<<NWORK, 256, GEMM_SMEM>>>(
        x16, wq16, bqkv, nullptr, N_QKV / 128, (N_QKV / 128) * (MTOK / 128),
        q16, k16, v16);

    // Persistent phase-continuous flash attention
    flash_mma_kernel<<<NWORK, 256, ATT_SMEM>>>(q16, k16, v16, y16);

    // Persistent proj GEMM: out = y @ Wproj + bproj (NX=8, 512 tiles)
    gemm_mma_kernel<0><<<NWORK, 256, GEMM_SMEM>>>(
        y16, wp16, bproj, out, CC / 128, (CC / 128) * (MTOK / 128),
        nullptr, nullptr, nullptr);
}

// round 17
// speedup vs baseline: 1.0546x; 1.0546x over previous
#include <cuda_runtime.h>
#include <cuda_fp16.h>
#include <math.h>
#include <stdint.h>

// Problem constants
#define BB 4
#define TT 2048
#define CC 1024
#define HH 16
#define DD 64
#define MTOK (BB * TT)          // 8192 tokens
#define N_QKV (3 * CC)          // 3072
#define NKC 16                  // 64-wide K blocks per 1024

#define LOG2E 1.4426950408889634f
#define NWORK 152               // persistent attention workers (GB300: 152 SMs)

// ---------------------------------------------------------------------------
// Scratch (allocation-free rule: __device__ globals) — fp16 single precision
// ---------------------------------------------------------------------------
__device__ __half g_x16[(size_t)MTOK * CC];
__device__ __half g_y16[(size_t)MTOK * CC];
__device__ __half g_wqkv16[(size_t)N_QKV * CC];
__device__ __half g_wproj16[(size_t)CC * CC];
// attention operand tiles (per (b,h), SW128 swizzled fp16)
__device__ __half g_q16[(size_t)BB * HH * 16 * 8192];
__device__ __half g_k16[(size_t)BB * HH * 16 * 8192];
__device__ __half g_v16[(size_t)BB * HH * 32 * 4096];

// ---------------------------------------------------------------------------
// PTX helpers (base sm_103 target — NO tcgen05)
// ---------------------------------------------------------------------------
__device__ __forceinline__ uint32_t smem_u32(const void* p) {
    uint32_t a;
    asm("{ .reg .u64 t; cvta.to.shared.u64 t, %1; cvt.u32.u64 %0, t; }" : "=r"(a) : "l"(p));
    return a;
}

#define SWZ128(off) ((off) ^ (((off) >> 3) & 0x70))

#define MBAR_INIT(addr, cnt) \
    asm volatile("mbarrier.init.shared.b64 [%0], %1;" :: "r"(addr), "r"(cnt) : "memory")

#define MBAR_EXPECT_TX(addr, bytes) \
    asm volatile("mbarrier.arrive.expect_tx.shared.b64 _, [%0], %1;" :: "r"(addr), "r"(bytes) : "memory")

#define MBAR_ARRIVE(addr) \
    asm volatile("mbarrier.arrive.shared.b64 _, [%0];" :: "r"(addr) : "memory")

__device__ __forceinline__ void mbar_wait(uint32_t mbar, uint32_t parity) {
    uint32_t done;
    asm volatile(
        "{\n\t.reg .pred p;\n\t"
        "mbarrier.try_wait.parity.acquire.cta.shared::cta.b64 p, [%1], %2;\n\t"
        "selp.b32 %0, 1, 0, p;\n\t}"
        : "=r"(done) : "r"(mbar), "r"(parity) : "memory");
    if (!done) {
        asm volatile(
            "{\n\t.reg .pred P1;\n\t"
            "WL_%=:\n\t"
            "mbarrier.try_wait.parity.acquire.cta.shared::cta.b64 P1, [%0], %1, 0x989680;\n\t"
            "@P1 bra.uni WD_%=;\n\t"
            "bra.uni WL_%=;\n\t"
            "WD_%=:\n\t}"
            :: "r"(mbar), "r"(parity) : "memory");
    }
}

__device__ __forceinline__ void bulk_g2s(uint32_t dst, const void* src, uint32_t bytes, uint32_t mbar) {
    asm volatile(
        "cp.async.bulk.shared::cluster.global.mbarrier::complete_tx::bytes [%0], [%1], %2, [%3];"
        :: "r"(dst), "l"(src), "r"(bytes), "r"(mbar) : "memory");
}

#define FENCE_ASYNC() asm volatile("fence.proxy.async.shared::cta;" ::: "memory")

__device__ __forceinline__ void ldsm_x4(uint32_t& r0, uint32_t& r1, uint32_t& r2, uint32_t& r3,
                                        uint32_t addr) {
    asm volatile("ldmatrix.sync.aligned.m8n8.x4.shared.b16 {%0,%1,%2,%3}, [%4];"
                 : "=r"(r0), "=r"(r1), "=r"(r2), "=r"(r3) : "r"(addr));
}

__device__ __forceinline__ void mma_f16(float* d, const uint32_t* a, const uint32_t* b) {
    asm volatile(
        "mma.sync.aligned.m16n8k16.row.col.f32.f16.f16.f32 "
        "{%0,%1,%2,%3}, {%4,%5,%6,%7}, {%8,%9}, {%0,%1,%2,%3};"
        : "+f"(d[0]), "+f"(d[1]), "+f"(d[2]), "+f"(d[3])
        : "r"(a[0]), "r"(a[1]), "r"(a[2]), "r"(a[3]), "r"(b[0]), "r"(b[1]));
}

__device__ __forceinline__ float ex2(float x) {
    float r;
    asm("ex2.approx.f32 %0, %1;" : "=f"(r) : "f"(x));
    return r;
}
__device__ __forceinline__ uint32_t ex2h2(uint32_t x) {
    uint32_t r;
    asm("ex2.approx.f16x2 %0, %1;" : "=r"(r) : "r"(x));
    return r;
}

__device__ __forceinline__ uint32_t packh2(float a, float b) {
    __half2 h = __floats2half2_rn(a, b);
    return *(uint32_t*)&h;
}

// ---------------------------------------------------------------------------
// Combined prep kernel (identical to R14)
// ---------------------------------------------------------------------------
__global__ __launch_bounds__(256) void prep_all_kernel(
    const float* __restrict__ x, __half* __restrict__ x16,
    const float* __restrict__ Wq, __half* __restrict__ wq16,
    const float* __restrict__ Wp, __half* __restrict__ wp16)
{
    __shared__ float s[64][128];
    const int id = blockIdx.x;
    const int t = threadIdx.x;

    if (id < 1024) {
        const int kc = id & 15;
        const int mt = id >> 4;
        const int r0 = t >> 3;
        const int c8 = t & 7;
        char* bh = (char*)(x16 + ((size_t)mt * NKC + kc) * 8192);
#pragma unroll
        for (int j = 0; j < 4; j++) {
            const int r = r0 + j * 32;
            const float* src = x + (size_t)(mt * 128 + r) * CC + kc * 64 + c8 * 8;
            float4 v0 = ((const float4*)src)[0];
            float4 v1 = ((const float4*)src)[1];
            __align__(16) __half h8[8];
            h8[0] = __float2half_rn(v0.x); h8[1] = __float2half_rn(v0.y);
            h8[2] = __float2half_rn(v0.z); h8[3] = __float2half_rn(v0.w);
            h8[4] = __float2half_rn(v1.x); h8[5] = __float2half_rn(v1.y);
            h8[6] = __float2half_rn(v1.z); h8[7] = __float2half_rn(v1.w);
            uint32_t off = SWZ128((uint32_t)(r * 128 + c8 * 16));
            *(uint4*)(bh + off) = *(const uint4*)h8;
        }
        return;
    }

    const bool isQ = (id < 1408);
    const int v = isQ ? (id - 1024) : (id - 1408);
    const int kc = v & 15;
    const int nt = v >> 4;
    const float* W = isQ ? Wq : Wp;
    __half* oh = isQ ? wq16 : wp16;
    const int N = isQ ? N_QKV : CC;

    for (int idx = t; idx < 64 * 128; idx += 256) {
        int r = idx >> 7, n = idx & 127;
        s[r][n] = W[(size_t)(kc * 64 + r) * N + nt * 128 + n];
    }
    __syncthreads();

    const int np = t & 127;
    const int c0 = (t >> 7) * 4;
    char* bh = (char*)(oh + ((size_t)nt * NKC + kc) * 8192);

#pragma unroll
    for (int c = c0; c < c0 + 4; c++) {
        __align__(16) __half h8[8];
#pragma unroll
        for (int j = 0; j < 8; j++) h8[j] = __float2half_rn(s[c * 8 + j][np]);
        uint32_t off = SWZ128((uint32_t)(np * 128 + c * 16));
        *(uint4*)(bh + off) = *(const uint4*)h8;
    }
}

// ---------------------------------------------------------------------------
// mma.sync fp16 GEMM: CTA 128x128, **4 warps of 64x64** (min smem redundancy:
// A 2x + B 2x = 64KB/chunk vs 96KB with 8x(64x32)). 128 threads, 2 CTAs/SM,
// BK=64, 3-stage pipeline, warp-elected empty arrives (count=4).
// MODE 0: fp32+bias. MODE 1: QKV fused epilogue.
// ---------------------------------------------------------------------------
#define G_STAGE 32768u      // A 16K | B 16K
#define G_NSTAGE 3
#define GEMM_SMEM (1024u + G_NSTAGE * G_STAGE)

template <int MODE>
__global__ __launch_bounds__(128, 2) void gemm_mma_kernel(
    const __half* __restrict__ A_, const __half* __restrict__ B_,
    const float* __restrict__ bias, float* __restrict__ C, int N,
    __half* __restrict__ oQ, __half* __restrict__ oK, __half* __restrict__ oV)
{
    extern __shared__ __align__(1024) char smem[];
    const uint32_t sbase = smem_u32(smem);
    const int tid = threadIdx.x;
    const int nt = blockIdx.x;
    const int mt = blockIdx.y;

    const uint32_t stage0 = sbase + 1024;

    if (tid == 0) {
#pragma unroll
        for (int s = 0; s < G_NSTAGE; s++) {
            MBAR_INIT(sbase + 8 + 8 * s, 1);       // full
            MBAR_INIT(sbase + 40 + 8 * s, 4);      // empty: one arrive per warp
        }
    }
    __syncthreads();

    const char* pA = (const char*)(A_ + (size_t)mt * NKC * 8192);
    const char* pB = (const char*)(B_ + (size_t)nt * NKC * 8192);

    if (tid == 0) {
#pragma unroll
        for (int c = 0; c < G_NSTAGE; c++) {
            uint32_t st = stage0 + c * G_STAGE;
            uint32_t mb = sbase + 8 + 8 * c;
            MBAR_EXPECT_TX(mb, G_STAGE);
            bulk_g2s(st + 0,     pA + (size_t)c * 16384, 16384, mb);
            bulk_g2s(st + 16384, pB + (size_t)c * 16384, 16384, mb);
        }
    }

    const int w = tid >> 5, l = tid & 31;
    const int mrow = (w >> 1) * 64;      // 0 or 64
    const int ncol = (w & 1) * 64;       // 0 or 64
    const int mat = l >> 3;
    const int rin = l & 7;

    const int a_row_off = rin + ((mat & 1) << 3);
    const int a_kb_off  = (mat >> 1) << 4;
    const int b_row_off = rin + ((mat >> 1) << 3);
    const int b_kb_off  = (mat & 1) << 4;

    float acc[4][8][4];
#pragma unroll
    for (int i = 0; i < 4; i++)
#pragma unroll
        for (int j = 0; j < 8; j++)
#pragma unroll
            for (int k = 0; k < 4; k++) acc[i][j][k] = 0.f;

    for (int c = 0; c < NKC; c++) {
        const int s = c % G_NSTAGE;
        const uint32_t ph = (uint32_t)((c / G_NSTAGE) & 1);
        mbar_wait(sbase + 8 + 8 * s, ph);

        const uint32_t stA = stage0 + s * G_STAGE;
        const uint32_t stB = stA + 16384;

#pragma unroll
        for (int ks = 0; ks < 4; ks++) {
            const int kb = ks * 32;
            uint32_t bf[8][2];
#pragma unroll
            for (int n16 = 0; n16 < 4; n16++) {
                int row = ncol + n16 * 16 + b_row_off;
                uint32_t off = (uint32_t)(row * 128) +
                               (uint32_t)((kb + b_kb_off) ^ ((row & 7) << 4));
                ldsm_x4(bf[n16 * 2][0], bf[n16 * 2][1],
                        bf[n16 * 2 + 1][0], bf[n16 * 2 + 1][1], stB + off);
            }
#pragma unroll
            for (int m16 = 0; m16 < 4; m16++) {
                int row = mrow + m16 * 16 + a_row_off;
                uint32_t off = (uint32_t)(row * 128) +
                               (uint32_t)((kb + a_kb_off) ^ ((row & 7) << 4));
                uint32_t a[4];
                ldsm_x4(a[0], a[1], a[2], a[3], stA + off);
#pragma unroll
                for (int n8 = 0; n8 < 8; n8++) mma_f16(acc[m16][n8], a, bf[n8]);
            }
        }

        if (l == 0) MBAR_ARRIVE(sbase + 40 + 8 * s);

        if (tid == 0 && c + G_NSTAGE < NKC) {
            mbar_wait(sbase + 40 + 8 * s, ph);
            FENCE_ASYNC();
            const int cn = c + G_NSTAGE;
            const uint32_t mb = sbase + 8 + 8 * s;
            const uint32_t st = stage0 + s * G_STAGE;
            MBAR_EXPECT_TX(mb, G_STAGE);
            bulk_g2s(st + 0,     pA + (size_t)cn * 16384, 16384, mb);
            bulk_g2s(st + 16384, pB + (size_t)cn * 16384, 16384, mb);
        }
    }

    const int lr = l >> 2;
    const int lc = (l & 3) * 2;

    if constexpr (MODE == 0) {
#pragma unroll
        for (int m16 = 0; m16 < 4; m16++) {
            const size_t r0 = (size_t)(mt * 128 + mrow + m16 * 16 + lr);
            float* c0p = C + r0 * N;
            float* c1p = c0p + (size_t)8 * N;
#pragma unroll
            for (int n8 = 0; n8 < 8; n8++) {
                const int col = nt * 128 + ncol + n8 * 8 + lc;
                const float bx = bias[col], by = bias[col + 1];
                float2 v0 = make_float2(acc[m16][n8][0] + bx, acc[m16][n8][1] + by);
                float2 v1 = make_float2(acc[m16][n8][2] + bx, acc[m16][n8][3] + by);
                *(float2*)(c0p + col) = v0;
                *(float2*)(c1p + col) = v1;
            }
        }
    } else {
        const int b_ = mt >> 4;
        const int qt_ = mt & 15;
        if (nt < 16) {
            const bool isQ = (nt < 8);
            __half* oh = isQ ? oQ : oK;
            const float scale = isQ ? (0.125f * LOG2E) : 1.0f;
            const int nth = isQ ? nt : nt - 8;
#pragma unroll
            for (int m16 = 0; m16 < 4; m16++) {
                const int rl0 = mrow + m16 * 16 + lr;
#pragma unroll
                for (int n8 = 0; n8 < 8; n8++) {
                    const int cl = ncol + n8 * 8 + lc;
                    const int hh2 = cl >> 6;
                    const int d = cl & 63;
                    const float bx = bias[nt * 128 + cl];
                    const float by = bias[nt * 128 + cl + 1];
                    const size_t tb = ((size_t)(b_ * HH + 2 * nth + hh2) * 16 + qt_) * 8192;
                    char* th = (char*)(oh + tb);
                    const uint32_t h0 = packh2((acc[m16][n8][0] + bx) * scale,
                                               (acc[m16][n8][1] + by) * scale);
                    const uint32_t off0 = SWZ128((uint32_t)(rl0 * 128 + d * 2));
                    *(uint32_t*)(th + off0) = h0;
                    const uint32_t h1 = packh2((acc[m16][n8][2] + bx) * scale,
                                               (acc[m16][n8][3] + by) * scale);
                    const uint32_t off1 = SWZ128((uint32_t)((rl0 + 8) * 128 + d * 2));
                    *(uint32_t*)(th + off1) = h1;
                }
            }
        } else {
            // V: transpose through smem (stages are free after the mainloop)
            float* sf = (float*)(smem + 1024);   // [128][129] fp32 = 66048 < 98304
            __syncthreads();
#pragma unroll
            for (int m16 = 0; m16 < 4; m16++) {
                const int rl0 = mrow + m16 * 16 + lr;
#pragma unroll
                for (int n8 = 0; n8 < 8; n8++) {
                    const int cl = ncol + n8 * 8 + lc;
                    const float bx = bias[nt * 128 + cl];
                    const float by = bias[nt * 128 + cl + 1];
                    sf[rl0 * 129 + cl]           = acc[m16][n8][0] + bx;
                    sf[rl0 * 129 + cl + 1]       = acc[m16][n8][1] + by;
                    sf[(rl0 + 8) * 129 + cl]     = acc[m16][n8][2] + bx;
                    sf[(rl0 + 8) * 129 + cl + 1] = acc[m16][n8][3] + by;
                }
            }
            __syncthreads();
            const int ntv = nt - 16;
            for (int it = tid; it < 2048; it += 128) {
                const int hh2 = it >> 10;
                const int rem = it & 1023;
                const int kt2loc = rem >> 9;
                const int d = (rem >> 3) & 63;
                const int oct = rem & 7;
                __align__(16) __half h8[8];
#pragma unroll
                for (int e = 0; e < 8; e++) {
                    const int key = kt2loc * 64 + oct * 8 + e;
                    h8[e] = __float2half_rn(sf[key * 129 + hh2 * 64 + d]);
                }
                const size_t tb =
                    ((size_t)(b_ * HH + 2 * ntv + hh2) * 32 + qt_ * 2 + kt2loc) * 4096;
                const uint32_t off = SWZ128((uint32_t)(d * 128 + oct * 16));
                *(uint4*)((char*)(oV + tb) + off) = *(const uint4*)h8;
            }
        }
    }
}

// ---------------------------------------------------------------------------
// PERSISTENT flash attention, PHASE-CONTINUOUS across jobs (identical to R14)
// ---------------------------------------------------------------------------
#define ATT_STAGE 32768u        // K 16K | V 16K
#define A_NSTAGE 5
#define ATT_SMEM  (1024u + 2u * 16384u + A_NSTAGE * ATT_STAGE)   // 197632 B
#define NJOBS 1024
#define ONESH2 0x3C003C00u      // half2(1.0, 1.0)

__global__ __launch_bounds__(256) void flash_mma_kernel(
    const __half* __restrict__ Q_, const __half* __restrict__ K_,
    const __half* __restrict__ V_, __half* __restrict__ oY)
{
    extern __shared__ __align__(1024) char smem[];
    const uint32_t sbase = smem_u32(smem);
    const int tid = threadIdx.x;
    const int worker = (int)blockIdx.x;

    const uint32_t mb_qf = sbase + 8;
    const uint32_t mb_qe = sbase + 24;
    const uint32_t mb_f  = sbase + 40;
    const uint32_t mb_e  = sbase + 88;
    const uint32_t sQ0 = sbase + 1024;
    const uint32_t stage0 = sbase + 1024 + 32768;

    if (tid == 0) {
        MBAR_INIT(mb_qf + 0, 1); MBAR_INIT(mb_qf + 8, 1);
        MBAR_INIT(mb_qe + 0, 8); MBAR_INIT(mb_qe + 8, 8);
#pragma unroll
        for (int s = 0; s < A_NSTAGE; s++) {
            MBAR_INIT(mb_f + 8 * s, 1);
            MBAR_INIT(mb_e + 8 * s, 8);
        }
    }
    __syncthreads();

    const int w = tid >> 5, l = tid & 31;
    const int mat = l >> 3, rin = l & 7;
    const int a_row_off = rin + ((mat & 1) << 3);
    const int a_kb_off  = (mat >> 1) << 4;
    const int b_row_off = rin + ((mat >> 1) << 3);
    const int b_kb_off  = (mat & 1) << 4;
    const int lr = l >> 2, qp = l & 3;

    const uint32_t ones[2] = {ONESH2, ONESH2};

    int pp = 0;
    int rank_p = worker;
    int kt_p = 0;
    int ntp = 16 - (rank_p >> 6);
    int jq = 0;
    int gp = 0;

    if (tid == 0) {
        mbar_wait(mb_qe + 0, 1);
        MBAR_EXPECT_TX(mb_qf + 0, 16384);
        {
            const int bhp = rank_p & 63;
            const int qtp = 15 - (rank_p >> 6);
            bulk_g2s(sQ0, (const char*)(Q_ + ((size_t)bhp * 16 + qtp) * 8192),
                     16384, mb_qf + 0);
        }
        jq = 1;
#pragma unroll
        for (int i = 0; i < A_NSTAGE; i++) {
            const int s = gp % A_NSTAGE;
            mbar_wait(mb_e + 8 * s, 1);
            FENCE_ASYNC();
            const uint32_t mb = mb_f + 8 * s;
            const uint32_t st = stage0 + s * ATT_STAGE;
            MBAR_EXPECT_TX(mb, ATT_STAGE);
            const int bhp = rank_p & 63;
            bulk_g2s(st + 0,
                     (const char*)(K_ + (size_t)bhp * 16 * 8192) + (size_t)kt_p * 16384,
                     16384, mb);
            bulk_g2s(st + 16384,
                     (const char*)(V_ + (size_t)bhp * 32 * 4096) + (size_t)kt_p * 16384,
                     16384, mb);
            kt_p++; gp++;
        }
    }

    int gc = 0;
    for (int p = 0;; p++) {
        const int rank = p * NWORK + ((p & 1) ? (NWORK - 1 - worker) : worker);
        if (rank >= NJOBS) break;
        const int qt = 15 - (rank >> 6);
        const int bh_idx = rank & 63;
        const int b = bh_idx >> 4;
        const int h = bh_idx & 15;
        const int ntiles = qt + 1;
        const int slot = p & 1;

        mbar_wait(mb_qf + 8 * slot, (uint32_t)((p >> 1) & 1));
        uint32_t qf[4][4];
#pragma unroll
        for (int ks = 0; ks < 4; ks++) {
            int row = w * 16 + a_row_off;
            uint32_t off = (uint32_t)(row * 128) +
                           (uint32_t)((ks * 32 + a_kb_off) ^ ((row & 7) << 4));
            ldsm_x4(qf[ks][0], qf[ks][1], qf[ks][2], qf[ks][3],
                    sQ0 + 16384u * slot + off);
        }
        if (l == 0) MBAR_ARRIVE(mb_qe + 8 * slot);

        float acc_o[8][4];
#pragma unroll
        for (int j = 0; j < 8; j++)
#pragma unroll
            for (int e = 0; e < 4; e++) acc_o[j][e] = 0.f;
        float acc_l[4] = {0.f, 0.f, 0.f, 0.f};
        float m0 = -1e30f, m1 = -1e30f;

        for (int kt = 0; kt < ntiles; kt++) {
            const int s = gc % A_NSTAGE;
            const uint32_t phs = (uint32_t)((gc / A_NSTAGE) & 1);
            mbar_wait(mb_f + 8 * s, phs);
            const uint32_t stK = stage0 + s * ATT_STAGE;
            const uint32_t stV = stK + 16384;

            float acc_s[16][4];
#pragma unroll
            for (int j = 0; j < 16; j++)
#pragma unroll
                for (int e = 0; e < 4; e++) acc_s[j][e] = 0.f;

#pragma unroll
            for (int ks = 0; ks < 4; ks++) {
                const uint32_t kb = (uint32_t)(ks * 32 + b_kb_off);
#pragma unroll
                for (int g = 0; g < 8; g++) {
                    int row = g * 16 + b_row_off;
                    uint32_t off = (uint32_t)(row * 128) + (kb ^ (uint32_t)((row & 7) << 4));
                    uint32_t kf[4];
                    ldsm_x4(kf[0], kf[1], kf[2], kf[3], stK + off);
                    mma_f16(acc_s[2 * g],     qf[ks], kf);
                    mma_f16(acc_s[2 * g + 1], qf[ks], kf + 2);
                }
            }

            if (kt == qt) {
                const int rr0 = w * 16 + lr, rr1 = rr0 + 8;
#pragma unroll
                for (int j = 0; j < 16; j++) {
                    const int c0 = j * 8 + qp * 2;
                    if (c0     > rr0) acc_s[j][0] = -1e30f;
                    if (c0 + 1 > rr0) acc_s[j][1] = -1e30f;
                    if (c0     > rr1) acc_s[j][2] = -1e30f;
                    if (c0 + 1 > rr1) acc_s[j][3] = -1e30f;
                }
            }

            float t0 = -1e30f, t1 = -1e30f;
#pragma unroll
            for (int j = 0; j < 16; j++) {
                t0 = fmaxf(t0, fmaxf(acc_s[j][0], acc_s[j][1]));
                t1 = fmaxf(t1, fmaxf(acc_s[j][2], acc_s[j][3]));
            }
            t0 = fmaxf(t0, __shfl_xor_sync(0xffffffffu, t0, 1));
            t0 = fmaxf(t0, __shfl_xor_sync(0xffffffffu, t0, 2));
            t1 = fmaxf(t1, __shfl_xor_sync(0xffffffffu, t1, 1));
            t1 = fmaxf(t1, __shfl_xor_sync(0xffffffffu, t1, 2));

            const float mn0 = fmaxf(m0, t0);
            const float mn1 = fmaxf(m1, t1);
            const float cr0 = ex2(m0 - mn0);
            const float cr1 = ex2(m1 - mn1);
            m0 = mn0; m1 = mn1;
            acc_l[0] *= cr0; acc_l[1] *= cr0;
            acc_l[2] *= cr1; acc_l[3] *= cr1;
#pragma unroll
            for (int j = 0; j < 8; j++) {
                acc_o[j][0] *= cr0; acc_o[j][1] *= cr0;
                acc_o[j][2] *= cr1; acc_o[j][3] *= cr1;
            }

#pragma unroll
            for (int kc = 0; kc < 8; kc++) {
                uint32_t pf[4];
#pragma unroll
                for (int jj = 0; jj < 2; jj++) {
                    const int j = 2 * kc + jj;
                    pf[jj * 2 + 0] = ex2h2(packh2(acc_s[j][0] - mn0, acc_s[j][1] - mn0));
                    pf[jj * 2 + 1] = ex2h2(packh2(acc_s[j][2] - mn1, acc_s[j][3] - mn1));
                }
                mma_f16(acc_l, pf, ones);

                const uint32_t vb = stV + ((kc < 4) ? 0u : 8192u);
                const uint32_t kb = (uint32_t)((kc & 3) * 32 + b_kb_off);
#pragma unroll
                for (int g = 0; g < 4; g++) {
                    int row = g * 16 + b_row_off;
                    uint32_t off = (uint32_t)(row * 128) + (kb ^ (uint32_t)((row & 7) << 4));
                    uint32_t vf[4];
                    ldsm_x4(vf[0], vf[1], vf[2], vf[3], vb + off);
                    mma_f16(acc_o[2 * g],     pf, vf);
                    mma_f16(acc_o[2 * g + 1], pf, vf + 2);
                }
            }

            if (l == 0) MBAR_ARRIVE(mb_e + 8 * s);

            if (tid == 0 && rank_p < NJOBS) {
                if (kt_p == ntp) {
                    pp++;
                    rank_p = pp * NWORK + ((pp & 1) ? (NWORK - 1 - worker) : worker);
                    if (rank_p < NJOBS) {
                        ntp = 16 - (rank_p >> 6);
                        kt_p = 0;
                        const int qslot = jq & 1;
                        mbar_wait(mb_qe + 8 * qslot, (uint32_t)(((jq >> 1) & 1) ^ 1));
                        FENCE_ASYNC();
                        MBAR_EXPECT_TX(mb_qf + 8 * qslot, 16384);
                        const int bhp = rank_p & 63;
                        const int qtp = 15 - (rank_p >> 6);
                        bulk_g2s(sQ0 + 16384u * qslot,
                                 (const char*)(Q_ + ((size_t)bhp * 16 + qtp) * 8192),
                                 16384, mb_qf + 8 * qslot);
                        jq++;
                    }
                }
                if (rank_p < NJOBS) {
                    const int sp = gp % A_NSTAGE;
                    mbar_wait(mb_e + 8 * sp, (uint32_t)(((gp / A_NSTAGE) & 1) ^ 1));
                    FENCE_ASYNC();
                    const uint32_t mb = mb_f + 8 * sp;
                    const uint32_t st = stage0 + sp * ATT_STAGE;
                    MBAR_EXPECT_TX(mb, ATT_STAGE);
                    const int bhp = rank_p & 63;
                    bulk_g2s(st + 0,
                             (const char*)(K_ + (size_t)bhp * 16 * 8192) +
                                 (size_t)kt_p * 16384, 16384, mb);
                    bulk_g2s(st + 16384,
                             (const char*)(V_ + (size_t)bhp * 32 * 4096) +
                                 (size_t)kt_p * 16384, 16384, mb);
                    kt_p++; gp++;
                }
            }
            gc++;
        }

        const float inv0 = 1.f / acc_l[0];
        const float inv1 = 1.f / acc_l[2];

        const size_t tb = ((size_t)(b * 16 + qt) * NKC + h) * 8192;
        char* th = (char*)(oY + tb);
        const int rl0 = w * 16 + lr;
#pragma unroll
        for (int j = 0; j < 8; j++) {
            const int dc = j * 8 + qp * 2;
            const uint32_t h0 = packh2(acc_o[j][0] * inv0, acc_o[j][1] * inv0);
            const uint32_t off0 = SWZ128((uint32_t)(rl0 * 128 + dc * 2));
            *(uint32_t*)(th + off0) = h0;
            const uint32_t h1 = packh2(acc_o[j][2] * inv1, acc_o[j][3] * inv1);
            const uint32_t off1 = SWZ128((uint32_t)((rl0 + 8) * 128 + dc * 2));
            *(uint32_t*)(th + off1) = h1;
        }
    }
}

// ---------------------------------------------------------------------------
// Launch
// ---------------------------------------------------------------------------
extern "C" void kernel_launch(void* const* d_in, const int* in_sizes, int n_in,
                              void* d_out, int out_size)
{
    const float* x     = (const float*)d_in[0];
    const float* Wqkv  = (const float*)d_in[1];
    const float* bqkv  = (const float*)d_in[2];
    const float* Wproj = (const float*)d_in[3];
    const float* bproj = (const float*)d_in[4];
    float* out = (float*)d_out;

    __half *x16, *y16, *wq16, *wp16, *q16, *k16, *v16;
    cudaGetSymbolAddress((void**)&x16, g_x16);
    cudaGetSymbolAddress((void**)&y16, g_y16);
    cudaGetSymbolAddress((void**)&wq16, g_wqkv16);
    cudaGetSymbolAddress((void**)&wp16, g_wproj16);
    cudaGetSymbolAddress((void**)&q16, g_q16);
    cudaGetSymbolAddress((void**)&k16, g_k16);
    cudaGetSymbolAddress((void**)&v16, g_v16);

    cudaFuncSetAttribute(gemm_mma_kernel<0>,
                         cudaFuncAttributeMaxDynamicSharedMemorySize, GEMM_SMEM);
    cudaFuncSetAttribute(gemm_mma_kernel<1>,
                         cudaFuncAttributeMaxDynamicSharedMemorySize, GEMM_SMEM);
    cudaFuncSetAttribute(flash_mma_kernel,
                         cudaFuncAttributeMaxDynamicSharedMemorySize, ATT_SMEM);

    // Combined prep (x + both weight transposes, fp16)
    prep_all_kernel<<<1536, 256>>>(x, x16, Wqkv, wq16, Wproj, wp16);

    // QKV GEMM with fused Q/K/V-tile epilogue (Q pre-scaled for exp2 softmax)
    gemm_mma_kernel<1><<<dim3(N_QKV / 128, MTOK / 128), 128, GEMM_SMEM>>>(
        x16, wq16, bqkv, nullptr, N_QKV, q16, k16, v16);

    // Persistent phase-continuous flash attention
    flash_mma_kernel<<<NWORK, 256, ATT_SMEM>>>(q16, k16, v16, y16);

    // Proj GEMM: out = y @ Wproj + bproj (fp32 epilogue)
    gemm_mma_kernel<0><<<dim3(CC / 128, MTOK / 128), 128, GEMM_SMEM>>>(
        y16, wp16, bproj, out, CC, nullptr, nullptr, nullptr);
}